// round 15
// baseline (speedup 1.0000x reference)
#include <cuda_runtime.h>
#include <cuda_bf16.h>
#include <cstdint>

// Problem constants
#define B_  64
#define T_  512
#define D_  128
#define H_  512
#define O_  256

#define NCTA 128          // 4 batch-groups x 32 j-groups
#define NTHR 256          // 8 warps
#define KTOT 640

// ---------------- device scratch ------------------------------------------
__device__ __align__(128) uint32_t g_hpk[(T_ + 1) * B_ * H_];   // packed h (hi|lo<<16), [t][b][j]
__device__ __align__(128) uint16_t g_xhi[T_ * B_ * D_];         // x hi, [t][b][d]
__device__ __align__(128) uint16_t g_xlo[T_ * B_ * D_];
__device__ __align__(128) uint16_t g_woThi[O_ * H_];            // Wo^T hi, [o][j]
__device__ __align__(128) uint16_t g_woTlo[O_ * H_];
__device__ __align__(128) unsigned g_flags[4][32];              // per-(bg, jg) step flags

// ---------------- PTX helpers ---------------------------------------------
__device__ __forceinline__ uint32_t smem_u32(const void* p) {
    uint32_t a;
    asm("{ .reg .u64 t; cvta.to.shared.u64 t, %1; cvt.u32.u64 %0, t; }" : "=r"(a) : "l"(p));
    return a;
}
__device__ __forceinline__ void cp16(uint32_t s, const void* g) {
    asm volatile("cp.async.cg.shared.global [%0], [%1], 16;" :: "r"(s), "l"(g));
}
#define CP_COMMIT() asm volatile("cp.async.commit_group;" ::: "memory")
#define CP_WAIT0()  asm volatile("cp.async.wait_group 0;" ::: "memory")

#define LDSM_X4(r0, r1, r2, r3, addr) \
    asm volatile("ldmatrix.sync.aligned.m8n8.x4.shared.b16 {%0,%1,%2,%3}, [%4];" \
        : "=r"(r0), "=r"(r1), "=r"(r2), "=r"(r3) : "r"(addr))

#define MMA_BF16(c, a0, a1, a2, a3, b0, b1) \
    asm volatile("mma.sync.aligned.m16n8k16.row.col.f32.bf16.bf16.f32 " \
        "{%0,%1,%2,%3}, {%4,%5,%6,%7}, {%8,%9}, {%0,%1,%2,%3};" \
        : "+f"((c)[0]), "+f"((c)[1]), "+f"((c)[2]), "+f"((c)[3]) \
        : "r"(a0), "r"(a1), "r"(a2), "r"(a3), "r"(b0), "r"(b1))

__device__ __forceinline__ uint32_t ldcg32(const uint16_t* p) {
    uint32_t v;
    asm volatile("ld.global.cg.u32 %0, [%1];" : "=r"(v) : "l"(p));
    return v;
}
__device__ __forceinline__ uint2 ldcg64(const uint32_t* p) {
    uint2 v;
    asm volatile("ld.global.cg.v2.u32 {%0,%1}, [%2];" : "=r"(v.x), "=r"(v.y) : "l"(p));
    return v;
}

__device__ __forceinline__ float sig_f(float x) {
    return __fdividef(1.0f, 1.0f + __expf(-x));
}
__device__ __forceinline__ float tanh_f(float x) {
    return __fdividef(2.0f, 1.0f + __expf(-2.0f * x)) - 1.0f;
}
__device__ __forceinline__ uint32_t pack_split(float v) {
    __nv_bfloat16 hb = __float2bfloat16(v);
    __nv_bfloat16 lb = __float2bfloat16(v - __bfloat162float(hb));
    return (uint32_t)__bfloat16_as_ushort(hb) | ((uint32_t)__bfloat16_as_ushort(lb) << 16);
}

// ---------------- prep ----------------------------------------------------
__global__ void prep_kernel(const float* __restrict__ x, const float* __restrict__ h0,
                            const float* __restrict__ Wo)
{
    int stride = gridDim.x * blockDim.x;
    int tid0 = blockIdx.x * blockDim.x + threadIdx.x;
    if (tid0 < 128) ((unsigned*)g_flags)[tid0] = 0;
    for (int i = tid0; i < T_ * B_ * D_; i += stride) {
        int d = i & (D_ - 1);
        int b = (i >> 7) & (B_ - 1);
        int t = i >> 13;
        float v = x[(b * T_ + t) * D_ + d];
        __nv_bfloat16 hb = __float2bfloat16(v);
        __nv_bfloat16 lb = __float2bfloat16(v - __bfloat162float(hb));
        g_xhi[i] = __bfloat16_as_ushort(hb);
        g_xlo[i] = __bfloat16_as_ushort(lb);
    }
    for (int i = tid0; i < B_ * H_; i += stride)
        g_hpk[i] = pack_split(h0[i]);
    for (int i = tid0; i < O_ * H_; i += stride) {
        int o = i >> 9, j = i & (H_ - 1);
        float v = Wo[j * O_ + o];
        __nv_bfloat16 hb = __float2bfloat16(v);
        __nv_bfloat16 lb = __float2bfloat16(v - __bfloat162float(hb));
        g_woThi[i] = __bfloat16_as_ushort(hb);
        g_woTlo[i] = __bfloat16_as_ushort(lb);
    }
}

// ---------------- lstm SMEM layout ----------------------------------------
#define BSTR      1296
#define ZSTR      68
#define ZPBUF     (16 * ZSTR)
#define SM_ZP     0
#define SM_ZP2    17408
#define SM_BB     34816
#define SMEM_TOTAL (SM_BB + 64 * BSTR)         // 117760

__global__ void __launch_bounds__(NTHR, 1)
lstm_kernel(const float* __restrict__ U,    // [H][4H]
            const float* __restrict__ W,    // [D][4H]
            const float* __restrict__ bias, // [4H]
            const float* __restrict__ c0)   // [B][H]
{
    extern __shared__ char smem[];
    const uint32_t sb = smem_u32(smem);

    const int tid  = threadIdx.x;
    const int wid  = tid >> 5;
    const int lane = tid & 31;
    const int bg   = blockIdx.x & 3;
    const int jg   = blockIdx.x >> 2;

    // ---- per-thread persistent state ----
    const int tb = tid >> 4;
    const int tj = tid & 15;
    const int gb = bg * 16 + tb;
    const int gj = jg * 16 + tj;
    float c_st = c0[gb * H_ + gj];
    const float bi  = bias[gj];
    const float bf  = bias[H_ + gj];
    const float bgc = bias[2 * H_ + gj];
    const float bo_ = bias[3 * H_ + gj];

    // ---- B fragments: two-pass build (hi, then lo); hoist to registers ----
    const uint32_t b_lane = sb + SM_BB
        + (uint32_t)((lane & 7) + (lane >> 4) * 8) * BSTR
        + (uint32_t)(((lane >> 3) & 1) * 16);
    uint32_t Bh[4][4][4], Bl[4][4][4];
    #pragma unroll
    for (int pass = 0; pass < 2; ++pass) {
        for (int n = 0; n < 64; ++n) {
            int col = (n & 3) * H_ + jg * 16 + (n >> 2);
            for (int k = tid; k < KTOT; k += NTHR) {
                if (pass == 1 && k >= H_) continue;
                float v = (k < H_) ? U[k * (4 * H_) + col] : W[(k - H_) * (4 * H_) + col];
                __nv_bfloat16 hb = __float2bfloat16(v);
                uint16_t outv = (pass == 0)
                    ? __bfloat16_as_ushort(hb)
                    : __bfloat16_as_ushort(__float2bfloat16(v - __bfloat162float(hb)));
                *(uint16_t*)(smem + SM_BB + n * BSTR + k * 2) = outv;
            }
        }
        __syncthreads();
        #pragma unroll
        for (int s = 0; s < 4; ++s) {
            uint32_t koff = (uint32_t)(128 * wid + 32 * s);
            #pragma unroll
            for (int g = 0; g < 4; ++g) {
                if (pass == 0) {
                    LDSM_X4(Bh[s][g][0], Bh[s][g][1], Bh[s][g][2], Bh[s][g][3],
                            b_lane + (uint32_t)(g * 16 * BSTR) + koff);
                } else {
                    LDSM_X4(Bl[s][g][0], Bl[s][g][1], Bl[s][g][2], Bl[s][g][3],
                            b_lane + (uint32_t)(g * 16 * BSTR) + koff);
                }
            }
        }
        __syncthreads();
    }
    // x-hi B-frags from the (still-hi) x rows, then overwrite x rows with lo
    uint32_t Bxh[4][4];
    {
        uint32_t koff = (uint32_t)(1024 + 32 * wid);
        #pragma unroll
        for (int g = 0; g < 4; ++g)
            LDSM_X4(Bxh[g][0], Bxh[g][1], Bxh[g][2], Bxh[g][3],
                    b_lane + (uint32_t)(g * 16 * BSTR) + koff);
    }
    __syncthreads();
    for (int n = 0; n < 64; ++n) {
        int col = (n & 3) * H_ + jg * 16 + (n >> 2);
        for (int k = H_ + tid; k < KTOT; k += NTHR) {
            float v = W[(k - H_) * (4 * H_) + col];
            __nv_bfloat16 hb = __float2bfloat16(v);
            *(uint16_t*)(smem + SM_BB + n * BSTR + k * 2) =
                __bfloat16_as_ushort(__float2bfloat16(v - __bfloat162float(hb)));
        }
    }
    __syncthreads();
    uint32_t Bxl[4][4];
    {
        uint32_t koff = (uint32_t)(1024 + 32 * wid);
        #pragma unroll
        for (int g = 0; g < 4; ++g)
            LDSM_X4(Bxl[g][0], Bxl[g][1], Bxl[g][2], Bxl[g][3],
                    b_lane + (uint32_t)(g * 16 * BSTR) + koff);
    }
    __syncthreads();

    // ---- fragment-row constants ----
    const int fr  = lane >> 2;
    const int cq  = (lane & 3) * 2;
    const int fb0 = bg * 16 + fr;
    const int fb1 = fb0 + 8;
    const int jb  = 64 * wid + cq;
    const int db  = 16 * wid + cq;

    // ---- x(0) A-fragment prefetch into registers ----
    uint32_t xa0, xa1, xa2, xa3, xq0, xq1, xq2, xq3;
    {
        const uint16_t* xh0 = g_xhi + (size_t)fb0 * D_;
        const uint16_t* xh1 = g_xhi + (size_t)fb1 * D_;
        const uint16_t* xl0 = g_xlo + (size_t)fb0 * D_;
        const uint16_t* xl1 = g_xlo + (size_t)fb1 * D_;
        xa0 = ldcg32(xh0 + db);     xa1 = ldcg32(xh1 + db);
        xa2 = ldcg32(xh0 + db + 8); xa3 = ldcg32(xh1 + db + 8);
        xq0 = ldcg32(xl0 + db);     xq1 = ldcg32(xl1 + db);
        xq2 = ldcg32(xl0 + db + 8); xq3 = ldcg32(xl1 + db + 8);
    }

    for (int t = 0; t < T_; ++t) {
        // ---- wait for h(t) FIRST: wid 0 polls all 32 flag slots ----
        if (wid == 0 && t > 0) {
            const volatile unsigned* fl = (const volatile unsigned*)g_flags[bg];
            unsigned tgt = (unsigned)t;
            while (!__all_sync(0xFFFFFFFFu, fl[lane] >= tgt)) { }
        }
        __syncthreads();                                  // [A]

        // ---- issue packed h loads immediately (latency hidden by x-MMAs) ----
        uint2 wv[4][4];
        {
            const size_t ho = (size_t)t * (B_ * H_);
            const uint32_t* hp0 = g_hpk + ho + (size_t)fb0 * H_;
            const uint32_t* hp1 = g_hpk + ho + (size_t)fb1 * H_;
            #pragma unroll
            for (int s = 0; s < 4; ++s) {
                int j0 = jb + 16 * s;
                wv[s][0] = ldcg64(hp0 + j0);
                wv[s][1] = ldcg64(hp1 + j0);
                wv[s][2] = ldcg64(hp0 + j0 + 8);
                wv[s][3] = ldcg64(hp1 + j0 + 8);
            }
        }

        float C[8][4];
        #pragma unroll
        for (int nt = 0; nt < 8; ++nt)
            #pragma unroll
            for (int i = 0; i < 4; ++i) C[nt][i] = 0.f;

        // ---- x phase (prefetched regs; runs while h loads are in flight) ----
        #pragma unroll
        for (int g = 0; g < 4; ++g) {
            MMA_BF16(C[2 * g],     xa0, xa1, xa2, xa3, Bxh[g][0], Bxh[g][1]);
            MMA_BF16(C[2 * g],     xq0, xq1, xq2, xq3, Bxh[g][0], Bxh[g][1]);
            MMA_BF16(C[2 * g],     xa0, xa1, xa2, xa3, Bxl[g][0], Bxl[g][1]);
            MMA_BF16(C[2 * g + 1], xa0, xa1, xa2, xa3, Bxh[g][2], Bxh[g][3]);
            MMA_BF16(C[2 * g + 1], xq0, xq1, xq2, xq3, Bxh[g][2], Bxh[g][3]);
            MMA_BF16(C[2 * g + 1], xa0, xa1, xa2, xa3, Bxl[g][2], Bxl[g][3]);
        }

        // ---- h phase: unpack + MMAs (operands arrive during x phase) ----
        {
            uint32_t ah[4][4], al[4][4];
            #pragma unroll
            for (int s = 0; s < 4; ++s) {
                ah[s][0] = __byte_perm(wv[s][0].x, wv[s][0].y, 0x5410);
                al[s][0] = __byte_perm(wv[s][0].x, wv[s][0].y, 0x7632);
                ah[s][1] = __byte_perm(wv[s][1].x, wv[s][1].y, 0x5410);
                al[s][1] = __byte_perm(wv[s][1].x, wv[s][1].y, 0x7632);
                ah[s][2] = __byte_perm(wv[s][2].x, wv[s][2].y, 0x5410);
                al[s][2] = __byte_perm(wv[s][2].x, wv[s][2].y, 0x7632);
                ah[s][3] = __byte_perm(wv[s][3].x, wv[s][3].y, 0x5410);
                al[s][3] = __byte_perm(wv[s][3].x, wv[s][3].y, 0x7632);
            }
            #pragma unroll
            for (int s = 0; s < 4; ++s) {
                #pragma unroll
                for (int g = 0; g < 4; ++g) {
                    MMA_BF16(C[2 * g],     ah[s][0], ah[s][1], ah[s][2], ah[s][3], Bh[s][g][0], Bh[s][g][1]);
                    MMA_BF16(C[2 * g],     al[s][0], al[s][1], al[s][2], al[s][3], Bh[s][g][0], Bh[s][g][1]);
                    MMA_BF16(C[2 * g],     ah[s][0], ah[s][1], ah[s][2], ah[s][3], Bl[s][g][0], Bl[s][g][1]);
                    MMA_BF16(C[2 * g + 1], ah[s][0], ah[s][1], ah[s][2], ah[s][3], Bh[s][g][2], Bh[s][g][3]);
                    MMA_BF16(C[2 * g + 1], al[s][0], al[s][1], al[s][2], al[s][3], Bh[s][g][2], Bh[s][g][3]);
                    MMA_BF16(C[2 * g + 1], ah[s][0], ah[s][1], ah[s][2], ah[s][3], Bl[s][g][2], Bl[s][g][3]);
                }
            }
        }

        // ---- prefetch x(t+1) A-fragments (consumed next step; deep slack) ----
        if (t + 1 < T_) {
            const size_t xo = (size_t)(t + 1) * (B_ * D_);
            const uint16_t* xh0 = g_xhi + xo + (size_t)fb0 * D_;
            const uint16_t* xh1 = g_xhi + xo + (size_t)fb1 * D_;
            const uint16_t* xl0 = g_xlo + xo + (size_t)fb0 * D_;
            const uint16_t* xl1 = g_xlo + xo + (size_t)fb1 * D_;
            xa0 = ldcg32(xh0 + db);     xa1 = ldcg32(xh1 + db);
            xa2 = ldcg32(xh0 + db + 8); xa3 = ldcg32(xh1 + db + 8);
            xq0 = ldcg32(xl0 + db);     xq1 = ldcg32(xl1 + db);
            xq2 = ldcg32(xl0 + db + 8); xq3 = ldcg32(xl1 + db + 8);
        }

        // ---- write K-partials to own buffer ----
        {
            float* zb = (wid < 4)
                ? (float*)(smem + SM_ZP)  + wid * ZPBUF
                : (float*)(smem + SM_ZP2) + (wid - 4) * ZPBUF;
            int r0 = lane >> 2;
            int cc = 2 * (lane & 3);
            #pragma unroll
            for (int nt = 0; nt < 8; ++nt) {
                int n0 = nt * 8 + cc;
                *(float2*)(zb + r0 * ZSTR + n0)       = make_float2(C[nt][0], C[nt][1]);
                *(float2*)(zb + (r0 + 8) * ZSTR + n0) = make_float2(C[nt][2], C[nt][3]);
            }
        }
        __syncthreads();                                  // [B]

        // ---- gates: one thread per (b, j); sum 8 partial buffers ----
        {
            float zi = bi, zf = bf, zg = bgc, zo = bo_;
            #pragma unroll
            for (int q = 0; q < 8; ++q) {
                const float* zb = (q < 4)
                    ? (const float*)(smem + SM_ZP)  + q * ZPBUF
                    : (const float*)(smem + SM_ZP2) + (q - 4) * ZPBUF;
                float4 v = *(const float4*)(zb + tb * ZSTR + tj * 4);
                zi += v.x; zf += v.y; zg += v.z; zo += v.w;
            }
            float ig = sig_f(zi);
            float fg = sig_f(zf);
            float gg = tanh_f(zg);
            float og = sig_f(zo);
            float cn = fg * c_st + ig * gg;
            c_st = cn;
            float hn = og * tanh_f(cn);
            size_t idx = ((size_t)(t + 1) * B_ + gb) * H_ + gj;
            g_hpk[idx] = pack_split(hn);
        }

        // ---- signal via split named barrier: warps 1-7 don't block ----
        if (wid != 0) {
            asm volatile("bar.arrive 1, %0;" :: "r"(NTHR) : "memory");
        } else {
            asm volatile("bar.sync 1, %0;" :: "r"(NTHR) : "memory");
            if (lane == 0) {
                __threadfence();
                *(volatile unsigned*)&g_flags[bg][jg] = (unsigned)(t + 1);
            }
        }
    }
}

// ---------------- HMMA output projection ----------------------------------
#define PSTRIDE 272
#define SMP_A   0
#define SMP_B   (128 * PSTRIDE)
#define SMEM_PROJ (SMP_B + 128 * PSTRIDE)       // 69632

__global__ void __launch_bounds__(256) proj_kernel(
    const float* __restrict__ bo,   // [O]
    float* __restrict__ out)        // [B][T][O]
{
    extern __shared__ char smem[];
    const uint32_t sbp = smem_u32(smem);
    const int t   = blockIdx.x;
    const int og  = blockIdx.y;
    const int tid = threadIdx.x;
    const int wid = tid >> 5;
    const int lane = tid & 31;

    const int m0 = (wid & 3) * 16;
    const int n0 = (wid >> 2) * 32;

    const uint32_t a_lane = sbp + SMP_A
        + (uint32_t)(m0 + (lane & 7) + ((lane >> 3) & 1) * 8) * PSTRIDE
        + (uint32_t)((lane >> 4) * 16);
    const uint32_t b_lane = sbp + SMP_B
        + (uint32_t)(n0 + (lane & 7) + (lane >> 4) * 8) * PSTRIDE
        + (uint32_t)(((lane >> 3) & 1) * 16);

    float C[4][4];
    #pragma unroll
    for (int nt = 0; nt < 4; ++nt)
        #pragma unroll
        for (int i = 0; i < 4; ++i) C[nt][i] = 0.f;

    const size_t hbase = (size_t)(t + 1) * B_ * H_;

    for (int jc = 0; jc < 4; ++jc) {
        // A: unpack packed h words into hi rows (b) and lo rows (b+64)
        #pragma unroll
        for (int i = tid; i < 4096; i += 256) {
            int b = i >> 6, jp = i & 63;
            const uint32_t* src = g_hpk + hbase + (size_t)b * H_ + jc * 128 + jp * 2;
            uint2 w = *(const uint2*)src;
            uint32_t hi = __byte_perm(w.x, w.y, 0x5410);
            uint32_t lo = __byte_perm(w.x, w.y, 0x7632);
            *(uint32_t*)(smem + SMP_A + b * PSTRIDE + jp * 4) = hi;
            *(uint32_t*)(smem + SMP_A + (b + 64) * PSTRIDE + jp * 4) = lo;
        }
        // B: Wo^T splits (rows o hi / o+64 lo) via cp.async
        #pragma unroll
        for (int i = tid; i < 2048; i += 256) {
            int row = i >> 4, c = i & 15;
            uint32_t dst = sbp + SMP_B + row * PSTRIDE + c * 16;
            const uint16_t* src = ((row < 64) ? g_woThi : g_woTlo)
                                + (size_t)(og * 64 + (row & 63)) * H_ + jc * 128 + c * 8;
            cp16(dst, src);
        }
        CP_COMMIT();
        CP_WAIT0();
        __syncthreads();

        #pragma unroll
        for (int s = 0; s < 8; ++s) {
            const uint32_t koff = (uint32_t)(s * 32);
            uint32_t ah0, ah1, ah2, ah3, al0, al1, al2, al3;
            LDSM_X4(ah0, ah1, ah2, ah3, a_lane + koff);
            LDSM_X4(al0, al1, al2, al3, a_lane + 64u * PSTRIDE + koff);
            uint32_t bh0, bh1, bh2, bh3, bh4, bh5, bh6, bh7;
            LDSM_X4(bh0, bh1, bh2, bh3, b_lane + koff);
            LDSM_X4(bh4, bh5, bh6, bh7, b_lane + 16u * PSTRIDE + koff);
            uint32_t bl0, bl1, bl2, bl3, bl4, bl5, bl6, bl7;
            LDSM_X4(bl0, bl1, bl2, bl3, b_lane + 64u * PSTRIDE + koff);
            LDSM_X4(bl4, bl5, bl6, bl7, b_lane + 80u * PSTRIDE + koff);
            MMA_BF16(C[0], ah0, ah1, ah2, ah3, bh0, bh1);
            MMA_BF16(C[0], al0, al1, al2, al3, bh0, bh1);
            MMA_BF16(C[0], ah0, ah1, ah2, ah3, bl0, bl1);
            MMA_BF16(C[1], ah0, ah1, ah2, ah3, bh2, bh3);
            MMA_BF16(C[1], al0, al1, al2, al3, bh2, bh3);
            MMA_BF16(C[1], ah0, ah1, ah2, ah3, bl2, bl3);
            MMA_BF16(C[2], ah0, ah1, ah2, ah3, bh4, bh5);
            MMA_BF16(C[2], al0, al1, al2, al3, bh4, bh5);
            MMA_BF16(C[2], ah0, ah1, ah2, ah3, bl4, bl5);
            MMA_BF16(C[3], ah0, ah1, ah2, ah3, bh6, bh7);
            MMA_BF16(C[3], al0, al1, al2, al3, bh6, bh7);
            MMA_BF16(C[3], ah0, ah1, ah2, ah3, bl6, bl7);
        }
        __syncthreads();
    }

    const int r0 = m0 + (lane >> 2);
    const int cbase = og * 64 + n0 + 2 * (lane & 3);
    #pragma unroll
    for (int nt = 0; nt < 4; ++nt) {
        int o = cbase + nt * 8;
        float2 bv = *(const float2*)(bo + o);
        *(float2*)(out + ((size_t)r0 * T_ + t) * O_ + o)
            = make_float2(C[nt][0] + bv.x, C[nt][1] + bv.y);
        *(float2*)(out + ((size_t)(r0 + 8) * T_ + t) * O_ + o)
            = make_float2(C[nt][2] + bv.x, C[nt][3] + bv.y);
    }
}

// ---------------- launch --------------------------------------------------
extern "C" void kernel_launch(void* const* d_in, const int* in_sizes, int n_in,
                              void* d_out, int out_size)
{
    const float* x   = (const float*)d_in[0];
    const float* h0  = (const float*)d_in[1];
    const float* c0  = (const float*)d_in[2];
    const float* W   = (const float*)d_in[3];
    const float* U   = (const float*)d_in[4];
    const float* bia = (const float*)d_in[5];
    const float* Wo  = (const float*)d_in[6];
    const float* bo  = (const float*)d_in[7];
    float* out = (float*)d_out;
    (void)in_sizes; (void)n_in; (void)out_size;

    cudaFuncSetAttribute(lstm_kernel,
                         cudaFuncAttributeMaxDynamicSharedMemorySize, SMEM_TOTAL);
    cudaFuncSetAttribute(proj_kernel,
                         cudaFuncAttributeMaxDynamicSharedMemorySize, SMEM_PROJ);

    prep_kernel<<<1024, 256>>>(x, h0, Wo);
    lstm_kernel<<<NCTA, NTHR, SMEM_TOTAL>>>(U, W, bia, c0);
    dim3 pg(T_, 4);
    proj_kernel<<<pg, 256, SMEM_PROJ>>>(bo, out);
}

// round 16
// speedup vs baseline: 1.2624x; 1.2624x over previous
#include <cuda_runtime.h>
#include <cuda_bf16.h>
#include <cstdint>

// Problem constants
#define B_  64
#define T_  512
#define D_  128
#define H_  512
#define O_  256

#define NCTA 128          // 4 batch-groups x 32 j-groups
#define NTHR 256          // 8 warps
#define KTOT 640

// ---------------- device scratch ------------------------------------------
__device__ __align__(128) uint32_t g_hpk[(T_ + 1) * B_ * H_];   // packed h (hi|lo<<16), [t][b][j]
__device__ __align__(128) uint16_t g_xhi[T_ * B_ * D_];         // x hi, [t][b][d]
__device__ __align__(128) uint16_t g_xlo[T_ * B_ * D_];
__device__ __align__(128) uint16_t g_woThi[O_ * H_];            // Wo^T hi, [o][j]
__device__ __align__(128) uint16_t g_woTlo[O_ * H_];
__device__ __align__(128) unsigned g_flags[4][32];              // per-(bg, jg) step flags

// ---------------- PTX helpers ---------------------------------------------
__device__ __forceinline__ uint32_t smem_u32(const void* p) {
    uint32_t a;
    asm("{ .reg .u64 t; cvta.to.shared.u64 t, %1; cvt.u32.u64 %0, t; }" : "=r"(a) : "l"(p));
    return a;
}
__device__ __forceinline__ void cp16(uint32_t s, const void* g) {
    asm volatile("cp.async.cg.shared.global [%0], [%1], 16;" :: "r"(s), "l"(g));
}
#define CP_COMMIT() asm volatile("cp.async.commit_group;" ::: "memory")
#define CP_WAIT0()  asm volatile("cp.async.wait_group 0;" ::: "memory")

#define LDSM_X4(r0, r1, r2, r3, addr) \
    asm volatile("ldmatrix.sync.aligned.m8n8.x4.shared.b16 {%0,%1,%2,%3}, [%4];" \
        : "=r"(r0), "=r"(r1), "=r"(r2), "=r"(r3) : "r"(addr))

#define MMA_BF16(c, a0, a1, a2, a3, b0, b1) \
    asm volatile("mma.sync.aligned.m16n8k16.row.col.f32.bf16.bf16.f32 " \
        "{%0,%1,%2,%3}, {%4,%5,%6,%7}, {%8,%9}, {%0,%1,%2,%3};" \
        : "+f"((c)[0]), "+f"((c)[1]), "+f"((c)[2]), "+f"((c)[3]) \
        : "r"(a0), "r"(a1), "r"(a2), "r"(a3), "r"(b0), "r"(b1))

__device__ __forceinline__ uint32_t ldcg32(const uint16_t* p) {
    uint32_t v;
    asm volatile("ld.global.cg.u32 %0, [%1];" : "=r"(v) : "l"(p));
    return v;
}
__device__ __forceinline__ uint2 ldcg64(const uint32_t* p) {
    uint2 v;
    asm volatile("ld.global.cg.v2.u32 {%0,%1}, [%2];" : "=r"(v.x), "=r"(v.y) : "l"(p));
    return v;
}

__device__ __forceinline__ float sig_f(float x) {
    return __fdividef(1.0f, 1.0f + __expf(-x));
}
__device__ __forceinline__ float tanh_f(float x) {
    return __fdividef(2.0f, 1.0f + __expf(-2.0f * x)) - 1.0f;
}
__device__ __forceinline__ uint32_t pack_split(float v) {
    __nv_bfloat16 hb = __float2bfloat16(v);
    __nv_bfloat16 lb = __float2bfloat16(v - __bfloat162float(hb));
    return (uint32_t)__bfloat16_as_ushort(hb) | ((uint32_t)__bfloat16_as_ushort(lb) << 16);
}

// ---------------- prep ----------------------------------------------------
__global__ void prep_kernel(const float* __restrict__ x, const float* __restrict__ h0,
                            const float* __restrict__ Wo)
{
    int stride = gridDim.x * blockDim.x;
    int tid0 = blockIdx.x * blockDim.x + threadIdx.x;
    if (tid0 < 128) ((unsigned*)g_flags)[tid0] = 0;
    for (int i = tid0; i < T_ * B_ * D_; i += stride) {
        int d = i & (D_ - 1);
        int b = (i >> 7) & (B_ - 1);
        int t = i >> 13;
        float v = x[(b * T_ + t) * D_ + d];
        __nv_bfloat16 hb = __float2bfloat16(v);
        __nv_bfloat16 lb = __float2bfloat16(v - __bfloat162float(hb));
        g_xhi[i] = __bfloat16_as_ushort(hb);
        g_xlo[i] = __bfloat16_as_ushort(lb);
    }
    for (int i = tid0; i < B_ * H_; i += stride)
        g_hpk[i] = pack_split(h0[i]);
    for (int i = tid0; i < O_ * H_; i += stride) {
        int o = i >> 9, j = i & (H_ - 1);
        float v = Wo[j * O_ + o];
        __nv_bfloat16 hb = __float2bfloat16(v);
        __nv_bfloat16 lb = __float2bfloat16(v - __bfloat162float(hb));
        g_woThi[i] = __bfloat16_as_ushort(hb);
        g_woTlo[i] = __bfloat16_as_ushort(lb);
    }
}

// ---------------- lstm SMEM layout ----------------------------------------
#define BSTR      1296
#define ZSTR      68
#define ZPBUF     (16 * ZSTR)
#define SM_ZP     0
#define SM_ZP2    17408
#define SM_BB     34816
#define SMEM_TOTAL (SM_BB + 64 * BSTR)         // 117760

__global__ void __launch_bounds__(NTHR, 1)
lstm_kernel(const float* __restrict__ U,    // [H][4H]
            const float* __restrict__ W,    // [D][4H]
            const float* __restrict__ bias, // [4H]
            const float* __restrict__ c0)   // [B][H]
{
    extern __shared__ char smem[];
    const uint32_t sb = smem_u32(smem);

    const int tid  = threadIdx.x;
    const int wid  = tid >> 5;
    const int lane = tid & 31;
    const int bg   = blockIdx.x & 3;
    const int jg   = blockIdx.x >> 2;

    // ---- per-thread persistent state ----
    const int tb = tid >> 4;
    const int tj = tid & 15;
    const int gb = bg * 16 + tb;
    const int gj = jg * 16 + tj;
    float c_st = c0[gb * H_ + gj];
    const float bi  = bias[gj];
    const float bf  = bias[H_ + gj];
    const float bgc = bias[2 * H_ + gj];
    const float bo_ = bias[3 * H_ + gj];

    // ---- B fragments: two-pass build (hi, then lo); hoist to registers ----
    const uint32_t b_lane = sb + SM_BB
        + (uint32_t)((lane & 7) + (lane >> 4) * 8) * BSTR
        + (uint32_t)(((lane >> 3) & 1) * 16);
    uint32_t Bh[4][4][4], Bl[4][4][4];
    #pragma unroll
    for (int pass = 0; pass < 2; ++pass) {
        for (int n = 0; n < 64; ++n) {
            int col = (n & 3) * H_ + jg * 16 + (n >> 2);
            for (int k = tid; k < KTOT; k += NTHR) {
                if (pass == 1 && k >= H_) continue;
                float v = (k < H_) ? U[k * (4 * H_) + col] : W[(k - H_) * (4 * H_) + col];
                __nv_bfloat16 hb = __float2bfloat16(v);
                uint16_t outv = (pass == 0)
                    ? __bfloat16_as_ushort(hb)
                    : __bfloat16_as_ushort(__float2bfloat16(v - __bfloat162float(hb)));
                *(uint16_t*)(smem + SM_BB + n * BSTR + k * 2) = outv;
            }
        }
        __syncthreads();
        #pragma unroll
        for (int s = 0; s < 4; ++s) {
            uint32_t koff = (uint32_t)(128 * wid + 32 * s);
            #pragma unroll
            for (int g = 0; g < 4; ++g) {
                if (pass == 0) {
                    LDSM_X4(Bh[s][g][0], Bh[s][g][1], Bh[s][g][2], Bh[s][g][3],
                            b_lane + (uint32_t)(g * 16 * BSTR) + koff);
                } else {
                    LDSM_X4(Bl[s][g][0], Bl[s][g][1], Bl[s][g][2], Bl[s][g][3],
                            b_lane + (uint32_t)(g * 16 * BSTR) + koff);
                }
            }
        }
        __syncthreads();
    }
    // x-hi B-frags from the (still-hi) x rows, then overwrite x rows with lo
    uint32_t Bxh[4][4];
    {
        uint32_t koff = (uint32_t)(1024 + 32 * wid);
        #pragma unroll
        for (int g = 0; g < 4; ++g)
            LDSM_X4(Bxh[g][0], Bxh[g][1], Bxh[g][2], Bxh[g][3],
                    b_lane + (uint32_t)(g * 16 * BSTR) + koff);
    }
    __syncthreads();
    for (int n = 0; n < 64; ++n) {
        int col = (n & 3) * H_ + jg * 16 + (n >> 2);
        for (int k = H_ + tid; k < KTOT; k += NTHR) {
            float v = W[(k - H_) * (4 * H_) + col];
            __nv_bfloat16 hb = __float2bfloat16(v);
            *(uint16_t*)(smem + SM_BB + n * BSTR + k * 2) =
                __bfloat16_as_ushort(__float2bfloat16(v - __bfloat162float(hb)));
        }
    }
    __syncthreads();
    uint32_t Bxl[4][4];
    {
        uint32_t koff = (uint32_t)(1024 + 32 * wid);
        #pragma unroll
        for (int g = 0; g < 4; ++g)
            LDSM_X4(Bxl[g][0], Bxl[g][1], Bxl[g][2], Bxl[g][3],
                    b_lane + (uint32_t)(g * 16 * BSTR) + koff);
    }
    __syncthreads();

    // ---- fragment-row constants ----
    const int fr  = lane >> 2;
    const int cq  = (lane & 3) * 2;
    const int fb0 = bg * 16 + fr;
    const int fb1 = fb0 + 8;
    const int jb  = 64 * wid + cq;
    const int db  = 16 * wid + cq;

    // ---- x(0) A-fragment prefetch into registers ----
    uint32_t xa0, xa1, xa2, xa3, xq0, xq1, xq2, xq3;
    {
        const uint16_t* xh0 = g_xhi + (size_t)fb0 * D_;
        const uint16_t* xh1 = g_xhi + (size_t)fb1 * D_;
        const uint16_t* xl0 = g_xlo + (size_t)fb0 * D_;
        const uint16_t* xl1 = g_xlo + (size_t)fb1 * D_;
        xa0 = ldcg32(xh0 + db);     xa1 = ldcg32(xh1 + db);
        xa2 = ldcg32(xh0 + db + 8); xa3 = ldcg32(xh1 + db + 8);
        xq0 = ldcg32(xl0 + db);     xq1 = ldcg32(xl1 + db);
        xq2 = ldcg32(xl0 + db + 8); xq3 = ldcg32(xl1 + db + 8);
    }

    for (int t = 0; t < T_; ++t) {
        float C[8][4];
        #pragma unroll
        for (int nt = 0; nt < 8; ++nt)
            #pragma unroll
            for (int i = 0; i < 4; ++i) C[nt][i] = 0.f;

        // ---- x phase (prefetched regs; overlaps the producer wait below) ----
        #pragma unroll
        for (int g = 0; g < 4; ++g) {
            MMA_BF16(C[2 * g],     xa0, xa1, xa2, xa3, Bxh[g][0], Bxh[g][1]);
            MMA_BF16(C[2 * g],     xq0, xq1, xq2, xq3, Bxh[g][0], Bxh[g][1]);
            MMA_BF16(C[2 * g],     xa0, xa1, xa2, xa3, Bxl[g][0], Bxl[g][1]);
            MMA_BF16(C[2 * g + 1], xa0, xa1, xa2, xa3, Bxh[g][2], Bxh[g][3]);
            MMA_BF16(C[2 * g + 1], xq0, xq1, xq2, xq3, Bxh[g][2], Bxh[g][3]);
            MMA_BF16(C[2 * g + 1], xa0, xa1, xa2, xa3, Bxl[g][2], Bxl[g][3]);
        }

        // ---- prefetch x(t+1) now (x regs dead; loads overlap the wait) ----
        if (t + 1 < T_) {
            const size_t xo = (size_t)(t + 1) * (B_ * D_);
            const uint16_t* xh0 = g_xhi + xo + (size_t)fb0 * D_;
            const uint16_t* xh1 = g_xhi + xo + (size_t)fb1 * D_;
            const uint16_t* xl0 = g_xlo + xo + (size_t)fb0 * D_;
            const uint16_t* xl1 = g_xlo + xo + (size_t)fb1 * D_;
            xa0 = ldcg32(xh0 + db);     xa1 = ldcg32(xh1 + db);
            xa2 = ldcg32(xh0 + db + 8); xa3 = ldcg32(xh1 + db + 8);
            xq0 = ldcg32(xl0 + db);     xq1 = ldcg32(xl1 + db);
            xq2 = ldcg32(xl0 + db + 8); xq3 = ldcg32(xl1 + db + 8);
        }

        // ---- block-wide wait for h(t): wid 0 polls all 32 flag slots ----
        if (wid == 0 && t > 0) {
            const volatile unsigned* fl = (const volatile unsigned*)g_flags[bg];
            unsigned tgt = (unsigned)t;
            while (!__all_sync(0xFFFFFFFFu, fl[lane] >= tgt)) { }
        }
        __syncthreads();                                  // [A]

        // ---- h phase: packed direct-LDG A frags, then MMAs ----
        {
            const size_t ho = (size_t)t * (B_ * H_);
            const uint32_t* hp0 = g_hpk + ho + (size_t)fb0 * H_;
            const uint32_t* hp1 = g_hpk + ho + (size_t)fb1 * H_;
            uint32_t ah[4][4], al[4][4];
            #pragma unroll
            for (int s = 0; s < 4; ++s) {
                int j0 = jb + 16 * s;
                uint2 wa = ldcg64(hp0 + j0);
                uint2 wb = ldcg64(hp1 + j0);
                uint2 wc = ldcg64(hp0 + j0 + 8);
                uint2 wd = ldcg64(hp1 + j0 + 8);
                ah[s][0] = __byte_perm(wa.x, wa.y, 0x5410); al[s][0] = __byte_perm(wa.x, wa.y, 0x7632);
                ah[s][1] = __byte_perm(wb.x, wb.y, 0x5410); al[s][1] = __byte_perm(wb.x, wb.y, 0x7632);
                ah[s][2] = __byte_perm(wc.x, wc.y, 0x5410); al[s][2] = __byte_perm(wc.x, wc.y, 0x7632);
                ah[s][3] = __byte_perm(wd.x, wd.y, 0x5410); al[s][3] = __byte_perm(wd.x, wd.y, 0x7632);
            }
            #pragma unroll
            for (int s = 0; s < 4; ++s) {
                #pragma unroll
                for (int g = 0; g < 4; ++g) {
                    MMA_BF16(C[2 * g],     ah[s][0], ah[s][1], ah[s][2], ah[s][3], Bh[s][g][0], Bh[s][g][1]);
                    MMA_BF16(C[2 * g],     al[s][0], al[s][1], al[s][2], al[s][3], Bh[s][g][0], Bh[s][g][1]);
                    MMA_BF16(C[2 * g],     ah[s][0], ah[s][1], ah[s][2], ah[s][3], Bl[s][g][0], Bl[s][g][1]);
                    MMA_BF16(C[2 * g + 1], ah[s][0], ah[s][1], ah[s][2], ah[s][3], Bh[s][g][2], Bh[s][g][3]);
                    MMA_BF16(C[2 * g + 1], al[s][0], al[s][1], al[s][2], al[s][3], Bh[s][g][2], Bh[s][g][3]);
                    MMA_BF16(C[2 * g + 1], ah[s][0], ah[s][1], ah[s][2], ah[s][3], Bl[s][g][2], Bl[s][g][3]);
                }
            }
        }

        // ---- write K-partials to own buffer ----
        {
            float* zb = (wid < 4)
                ? (float*)(smem + SM_ZP)  + wid * ZPBUF
                : (float*)(smem + SM_ZP2) + (wid - 4) * ZPBUF;
            int r0 = lane >> 2;
            int cc = 2 * (lane & 3);
            #pragma unroll
            for (int nt = 0; nt < 8; ++nt) {
                int n0 = nt * 8 + cc;
                *(float2*)(zb + r0 * ZSTR + n0)       = make_float2(C[nt][0], C[nt][1]);
                *(float2*)(zb + (r0 + 8) * ZSTR + n0) = make_float2(C[nt][2], C[nt][3]);
            }
        }
        __syncthreads();                                  // [B]

        // ---- gates: one thread per (b, j); sum 8 partial buffers ----
        {
            float zi = bi, zf = bf, zg = bgc, zo = bo_;
            #pragma unroll
            for (int q = 0; q < 8; ++q) {
                const float* zb = (q < 4)
                    ? (const float*)(smem + SM_ZP)  + q * ZPBUF
                    : (const float*)(smem + SM_ZP2) + (q - 4) * ZPBUF;
                float4 v = *(const float4*)(zb + tb * ZSTR + tj * 4);
                zi += v.x; zf += v.y; zg += v.z; zo += v.w;
            }
            float ig = sig_f(zi);
            float fg = sig_f(zf);
            float gg = tanh_f(zg);
            float og = sig_f(zo);
            float cn = fg * c_st + ig * gg;
            c_st = cn;
            float hn = og * tanh_f(cn);
            size_t idx = ((size_t)(t + 1) * B_ + gb) * H_ + gj;
            g_hpk[idx] = pack_split(hn);
        }

        // ---- signal via split named barrier: warps 1-7 don't block ----
        if (wid != 0) {
            asm volatile("bar.arrive 1, %0;" :: "r"(NTHR) : "memory");
        } else {
            asm volatile("bar.sync 1, %0;" :: "r"(NTHR) : "memory");
            if (lane == 0) {
                __threadfence();
                *(volatile unsigned*)&g_flags[bg][jg] = (unsigned)(t + 1);
            }
        }
    }
}

// ---------------- HMMA output projection ----------------------------------
#define PSTRIDE 272
#define SMP_A   0
#define SMP_B   (128 * PSTRIDE)
#define SMEM_PROJ (SMP_B + 128 * PSTRIDE)       // 69632

__global__ void __launch_bounds__(256) proj_kernel(
    const float* __restrict__ bo,   // [O]
    float* __restrict__ out)        // [B][T][O]
{
    extern __shared__ char smem[];
    const uint32_t sbp = smem_u32(smem);
    const int t   = blockIdx.x;
    const int og  = blockIdx.y;
    const int tid = threadIdx.x;
    const int wid = tid >> 5;
    const int lane = tid & 31;

    const int m0 = (wid & 3) * 16;
    const int n0 = (wid >> 2) * 32;

    const uint32_t a_lane = sbp + SMP_A
        + (uint32_t)(m0 + (lane & 7) + ((lane >> 3) & 1) * 8) * PSTRIDE
        + (uint32_t)((lane >> 4) * 16);
    const uint32_t b_lane = sbp + SMP_B
        + (uint32_t)(n0 + (lane & 7) + (lane >> 4) * 8) * PSTRIDE
        + (uint32_t)(((lane >> 3) & 1) * 16);

    float C[4][4];
    #pragma unroll
    for (int nt = 0; nt < 4; ++nt)
        #pragma unroll
        for (int i = 0; i < 4; ++i) C[nt][i] = 0.f;

    const size_t hbase = (size_t)(t + 1) * B_ * H_;

    for (int jc = 0; jc < 4; ++jc) {
        // A: unpack packed h words into hi rows (b) and lo rows (b+64)
        #pragma unroll
        for (int i = tid; i < 4096; i += 256) {
            int b = i >> 6, jp = i & 63;
            const uint32_t* src = g_hpk + hbase + (size_t)b * H_ + jc * 128 + jp * 2;
            uint2 w = *(const uint2*)src;
            uint32_t hi = __byte_perm(w.x, w.y, 0x5410);
            uint32_t lo = __byte_perm(w.x, w.y, 0x7632);
            *(uint32_t*)(smem + SMP_A + b * PSTRIDE + jp * 4) = hi;
            *(uint32_t*)(smem + SMP_A + (b + 64) * PSTRIDE + jp * 4) = lo;
        }
        // B: Wo^T splits (rows o hi / o+64 lo) via cp.async
        #pragma unroll
        for (int i = tid; i < 2048; i += 256) {
            int row = i >> 4, c = i & 15;
            uint32_t dst = sbp + SMP_B + row * PSTRIDE + c * 16;
            const uint16_t* src = ((row < 64) ? g_woThi : g_woTlo)
                                + (size_t)(og * 64 + (row & 63)) * H_ + jc * 128 + c * 8;
            cp16(dst, src);
        }
        CP_COMMIT();
        CP_WAIT0();
        __syncthreads();

        #pragma unroll
        for (int s = 0; s < 8; ++s) {
            const uint32_t koff = (uint32_t)(s * 32);
            uint32_t ah0, ah1, ah2, ah3, al0, al1, al2, al3;
            LDSM_X4(ah0, ah1, ah2, ah3, a_lane + koff);
            LDSM_X4(al0, al1, al2, al3, a_lane + 64u * PSTRIDE + koff);
            uint32_t bh0, bh1, bh2, bh3, bh4, bh5, bh6, bh7;
            LDSM_X4(bh0, bh1, bh2, bh3, b_lane + koff);
            LDSM_X4(bh4, bh5, bh6, bh7, b_lane + 16u * PSTRIDE + koff);
            uint32_t bl0, bl1, bl2, bl3, bl4, bl5, bl6, bl7;
            LDSM_X4(bl0, bl1, bl2, bl3, b_lane + 64u * PSTRIDE + koff);
            LDSM_X4(bl4, bl5, bl6, bl7, b_lane + 80u * PSTRIDE + koff);
            MMA_BF16(C[0], ah0, ah1, ah2, ah3, bh0, bh1);
            MMA_BF16(C[0], al0, al1, al2, al3, bh0, bh1);
            MMA_BF16(C[0], ah0, ah1, ah2, ah3, bl0, bl1);
            MMA_BF16(C[1], ah0, ah1, ah2, ah3, bh2, bh3);
            MMA_BF16(C[1], al0, al1, al2, al3, bh2, bh3);
            MMA_BF16(C[1], ah0, ah1, ah2, ah3, bl2, bl3);
            MMA_BF16(C[2], ah0, ah1, ah2, ah3, bh4, bh5);
            MMA_BF16(C[2], al0, al1, al2, al3, bh4, bh5);
            MMA_BF16(C[2], ah0, ah1, ah2, ah3, bl4, bl5);
            MMA_BF16(C[3], ah0, ah1, ah2, ah3, bh6, bh7);
            MMA_BF16(C[3], al0, al1, al2, al3, bh6, bh7);
            MMA_BF16(C[3], ah0, ah1, ah2, ah3, bl6, bl7);
        }
        __syncthreads();
    }

    const int r0 = m0 + (lane >> 2);
    const int cbase = og * 64 + n0 + 2 * (lane & 3);
    #pragma unroll
    for (int nt = 0; nt < 4; ++nt) {
        int o = cbase + nt * 8;
        float2 bv = *(const float2*)(bo + o);
        *(float2*)(out + ((size_t)r0 * T_ + t) * O_ + o)
            = make_float2(C[nt][0] + bv.x, C[nt][1] + bv.y);
        *(float2*)(out + ((size_t)(r0 + 8) * T_ + t) * O_ + o)
            = make_float2(C[nt][2] + bv.x, C[nt][3] + bv.y);
    }
}

// ---------------- launch --------------------------------------------------
extern "C" void kernel_launch(void* const* d_in, const int* in_sizes, int n_in,
                              void* d_out, int out_size)
{
    const float* x   = (const float*)d_in[0];
    const float* h0  = (const float*)d_in[1];
    const float* c0  = (const float*)d_in[2];
    const float* W   = (const float*)d_in[3];
    const float* U   = (const float*)d_in[4];
    const float* bia = (const float*)d_in[5];
    const float* Wo  = (const float*)d_in[6];
    const float* bo  = (const float*)d_in[7];
    float* out = (float*)d_out;
    (void)in_sizes; (void)n_in; (void)out_size;

    cudaFuncSetAttribute(lstm_kernel,
                         cudaFuncAttributeMaxDynamicSharedMemorySize, SMEM_TOTAL);
    cudaFuncSetAttribute(proj_kernel,
                         cudaFuncAttributeMaxDynamicSharedMemorySize, SMEM_PROJ);

    prep_kernel<<<1024, 256>>>(x, h0, Wo);
    lstm_kernel<<<NCTA, NTHR, SMEM_TOTAL>>>(U, W, bia, c0);
    dim3 pg(T_, 4);
    proj_kernel<<<pg, 256, SMEM_PROJ>>>(bo, out);
}